// round 6
// baseline (speedup 1.0000x reference)
#include <cuda_runtime.h>
#include <cuda_bf16.h>
#include <math.h>

// Problem dims (fixed by the dataset)
#define Bc   8
#define Cc   512
#define Hc   96
#define Wc   144
#define HWc  (Hc * Wc)          // 13824
#define Ntok (Bc * HWc)         // 110592
#define Dd   512
#define Mm   512

#define BK     16
#define BS_LD  516              // padded Bs row stride (floats)

// Scratch (allocation-free rule: __device__ globals)
__device__ float g_q[(size_t)Ntok * Dd];   // normalized q, [N, D] row-major
__device__ float g_inv[Ntok];              // 1/norm per token
__device__ float g_colsum[Mm];             // column softmax denominators

// ---------------------------------------------------------------------------
// K1: per-token inverse L2 norm over channels (coalesced along hw), + zero colsum
// ---------------------------------------------------------------------------
__global__ void k_norm(const float* __restrict__ x) {
    int n = blockIdx.x * 256 + threadIdx.x;
    // Zero ALL 512 colsum entries from the 256 threads of block 0
    // (previous bug: only 0..255 were zeroed -> accumulation across graph replays)
    if (blockIdx.x == 0) {
        g_colsum[threadIdx.x]       = 0.0f;
        g_colsum[threadIdx.x + 256] = 0.0f;
    }
    if (n >= Ntok) return;
    int b = n / HWc, hw = n % HWc;
    const float* p = x + (size_t)b * Cc * HWc + hw;
    float s = 0.0f;
#pragma unroll 8
    for (int c = 0; c < Cc; c++) {
        float v = p[(size_t)c * HWc];
        s += v * v;
    }
    g_inv[n] = 1.0f / fmaxf(sqrtf(s), 1e-12f);
}

// ---------------------------------------------------------------------------
// K2: transpose [B,C,HW] -> g_q [N,D] with normalization, 32x32 smem tiles
// ---------------------------------------------------------------------------
__global__ void k_qt(const float* __restrict__ x) {
    __shared__ float tile[32][33];
    int b   = blockIdx.z;
    int hw0 = blockIdx.x * 32;
    int d0  = blockIdx.y * 32;
    for (int r = threadIdx.y; r < 32; r += 8)
        tile[r][threadIdx.x] =
            x[((size_t)(b * Cc + d0 + r)) * HWc + hw0 + threadIdx.x];
    __syncthreads();
    for (int r = threadIdx.y; r < 32; r += 8) {
        int n = b * HWc + hw0 + r;
        g_q[(size_t)n * Dd + d0 + threadIdx.x] = tile[threadIdx.x][r] * g_inv[n];
    }
}

// ---------------------------------------------------------------------------
// K3: GEMM1 (score = q . mem^T) fused with exp, row softmax, colsum reduction,
//     and both score outputs. CTA tile: 32 tokens x 512 slots, 256 threads,
//     8x8 micro-tile per thread (split 4+4 in each dim for conflict-free LDS).
// ---------------------------------------------------------------------------
__global__ void __launch_bounds__(256)
k_gemm1(const float* __restrict__ pmem,
        float* __restrict__ out_sq,
        float* __restrict__ out_sm) {
    __shared__ float As[BK][36];
    __shared__ float Bs[BK][BS_LD];
    __shared__ float rs[32];
    __shared__ float cs[Mm];

    int tid = threadIdx.x;
    int sg = tid & 63;          // slot group 0..63
    int tg = tid >> 6;          // token group 0..3
    int n0 = blockIdx.x * 32;

    float acc[8][8];
#pragma unroll
    for (int i = 0; i < 8; i++)
#pragma unroll
        for (int j = 0; j < 8; j++) acc[i][j] = 0.0f;

    for (int k0 = 0; k0 < Dd; k0 += BK) {
        // A tile: As[kk][t] = g_q[(n0+t)*D + k0+kk]  (float2 per thread)
        {
            int t  = tid >> 3;
            int kk = (tid & 7) * 2;
            const float* src = &g_q[(size_t)(n0 + t) * Dd + k0 + kk];
            As[kk][t]     = src[0];
            As[kk + 1][t] = src[1];
        }
        // B tile (transposed): Bs[kk][m] = mem[m*D + k0+kk]
        {
            int q = tid & 3;
            int mb = tid >> 2;
#pragma unroll
            for (int rr = 0; rr < 8; rr++) {
                int m = mb + rr * 64;
                float4 v = *(const float4*)&pmem[(size_t)m * Dd + k0 + q * 4];
                Bs[q * 4 + 0][m] = v.x;
                Bs[q * 4 + 1][m] = v.y;
                Bs[q * 4 + 2][m] = v.z;
                Bs[q * 4 + 3][m] = v.w;
            }
        }
        __syncthreads();
#pragma unroll
        for (int kk = 0; kk < BK; kk++) {
            float4 a0 = *(const float4*)&As[kk][tg * 4];
            float4 a1 = *(const float4*)&As[kk][16 + tg * 4];
            float4 b0 = *(const float4*)&Bs[kk][sg * 4];
            float4 b1 = *(const float4*)&Bs[kk][256 + sg * 4];
            float av[8] = {a0.x, a0.y, a0.z, a0.w, a1.x, a1.y, a1.z, a1.w};
            float bv[8] = {b0.x, b0.y, b0.z, b0.w, b1.x, b1.y, b1.z, b1.w};
#pragma unroll
            for (int i = 0; i < 8; i++)
#pragma unroll
                for (int j = 0; j < 8; j++)
                    acc[i][j] += av[i] * bv[j];
        }
        __syncthreads();
    }

    // ---- epilogue: exp, row/col reductions, stores ----
#pragma unroll
    for (int i = 0; i < 8; i++)
#pragma unroll
        for (int j = 0; j < 8; j++) acc[i][j] = expf(acc[i][j]);

    if (tid < 32) rs[tid] = 0.0f;
    cs[tid]       = 0.0f;
    cs[tid + 256] = 0.0f;
    __syncthreads();

#pragma unroll
    for (int i = 0; i < 8; i++) {
        float p = 0.0f;
#pragma unroll
        for (int j = 0; j < 8; j++) p += acc[i][j];
        int t = (i >> 2) * 16 + tg * 4 + (i & 3);
        atomicAdd(&rs[t], p);
    }
#pragma unroll
    for (int j = 0; j < 8; j++) {
        float p = 0.0f;
#pragma unroll
        for (int i = 0; i < 8; i++) p += acc[i][j];
        int m = (j >> 2) * 256 + sg * 4 + (j & 3);
        atomicAdd(&cs[m], p);
    }
    __syncthreads();

    atomicAdd(&g_colsum[tid],       cs[tid]);
    atomicAdd(&g_colsum[tid + 256], cs[tid + 256]);

#pragma unroll
    for (int i = 0; i < 8; i++) {
        int t = (i >> 2) * 16 + tg * 4 + (i & 3);
        size_t n = (size_t)(n0 + t);
        float rinv = 1.0f / rs[t];
#pragma unroll
        for (int sh = 0; sh < 2; sh++) {
            int m = sh * 256 + sg * 4;
            float4 e = make_float4(acc[i][sh * 4 + 0], acc[i][sh * 4 + 1],
                                   acc[i][sh * 4 + 2], acc[i][sh * 4 + 3]);
            *(float4*)&out_sq[n * Mm + m] = e;   // unnormalized exp; scaled in K5
            float4 pv = make_float4(e.x * rinv, e.y * rinv, e.z * rinv, e.w * rinv);
            *(float4*)&out_sm[n * Mm + m] = pv;  // row softmax (final)
        }
    }
}

// ---------------------------------------------------------------------------
// K4: GEMM2 (upd = P . mem), same tile skeleton; B tile is a straight copy.
//     Output written in [B, D, H, W] layout via chunked smem transpose.
// ---------------------------------------------------------------------------
__global__ void __launch_bounds__(256)
k_gemm2(const float* __restrict__ pmem,
        const float* __restrict__ Pmat,
        float* __restrict__ out_upd) {
    __shared__ float As[BK][36];
    __shared__ float Bs[BK][BS_LD];
    __shared__ float sT[32][33];

    int tid = threadIdx.x;
    int sg = tid & 63;
    int tg = tid >> 6;
    int n0 = blockIdx.x * 32;

    float acc[8][8];
#pragma unroll
    for (int i = 0; i < 8; i++)
#pragma unroll
        for (int j = 0; j < 8; j++) acc[i][j] = 0.0f;

    for (int k0 = 0; k0 < Mm; k0 += BK) {
        {
            int t  = tid >> 3;
            int kk = (tid & 7) * 2;
            const float* src = &Pmat[(size_t)(n0 + t) * Mm + k0 + kk];
            As[kk][t]     = src[0];
            As[kk + 1][t] = src[1];
        }
        // Bs[kk][d] = mem[(k0+kk)*D + d]  (straight float4 copy)
        {
            int kk = tid >> 7;          // 0..1
            int d4 = (tid & 127) * 4;   // 0..508
#pragma unroll
            for (int rr = 0; rr < 8; rr++) {
                int k = kk + rr * 2;
                float4 v = *(const float4*)&pmem[(size_t)(k0 + k) * Dd + d4];
                *(float4*)&Bs[k][d4] = v;
            }
        }
        __syncthreads();
#pragma unroll
        for (int kk = 0; kk < BK; kk++) {
            float4 a0 = *(const float4*)&As[kk][tg * 4];
            float4 a1 = *(const float4*)&As[kk][16 + tg * 4];
            float4 b0 = *(const float4*)&Bs[kk][sg * 4];
            float4 b1 = *(const float4*)&Bs[kk][256 + sg * 4];
            float av[8] = {a0.x, a0.y, a0.z, a0.w, a1.x, a1.y, a1.z, a1.w};
            float bv[8] = {b0.x, b0.y, b0.z, b0.w, b1.x, b1.y, b1.z, b1.w};
#pragma unroll
            for (int i = 0; i < 8; i++)
#pragma unroll
                for (int j = 0; j < 8; j++)
                    acc[i][j] += av[i] * bv[j];
        }
        __syncthreads();
    }

    // Output transpose: upd[(b*D + d)*HW + hw], coalesced via 32-d chunks.
    int b   = n0 / HWc;
    int hw0 = n0 % HWc;
    for (int c = 0; c < 16; c++) {
        int sh   = c >> 3;
        int sglo = (c & 7) * 8;
        if (sg >= sglo && sg < sglo + 8) {
#pragma unroll
            for (int i = 0; i < 8; i++) {
                int t = (i >> 2) * 16 + tg * 4 + (i & 3);
#pragma unroll
                for (int j = 0; j < 4; j++) {
                    int dl = (sg - sglo) * 4 + j;
                    sT[dl][t] = acc[i][sh * 4 + j];
                }
            }
        }
        __syncthreads();
        {
            int t = tid & 31;
#pragma unroll
            for (int r = 0; r < 4; r++) {
                int dl = (tid >> 5) + r * 8;
                int d  = c * 32 + dl;
                out_upd[((size_t)(b * Dd + d)) * HWc + hw0 + t] = sT[dl][t];
            }
        }
        __syncthreads();
    }
}

// ---------------------------------------------------------------------------
// K5: scale unnormalized exp by 1/colsum (column softmax finalization)
// ---------------------------------------------------------------------------
__global__ void k_scale(float* __restrict__ out_sq) {
    __shared__ float cinv[Mm];
    int tid = threadIdx.x;
    cinv[tid]       = 1.0f / g_colsum[tid];
    cinv[tid + 256] = 1.0f / g_colsum[tid + 256];
    __syncthreads();
    size_t total4 = (size_t)Ntok * Mm / 4;
    for (size_t i = (size_t)blockIdx.x * 256 + tid; i < total4;
         i += (size_t)gridDim.x * 256) {
        float4 v = ((float4*)out_sq)[i];
        int m = (int)((i * 4) & (Mm - 1));
        v.x *= cinv[m];
        v.y *= cinv[m + 1];
        v.z *= cinv[m + 2];
        v.w *= cinv[m + 3];
        ((float4*)out_sq)[i] = v;
    }
}

// ---------------------------------------------------------------------------
extern "C" void kernel_launch(void* const* d_in, const int* in_sizes, int n_in,
                              void* d_out, int out_size) {
    const float* x    = (const float*)d_in[0];   // query_source [8,512,96,144]
    const float* pmem = (const float*)d_in[1];   // memory [512,512]
    float* out = (float*)d_out;

    const size_t ND = (size_t)Ntok * Dd;         // 56,623,104
    float* out_upd = out;                        // [B, D, H, W]
    float* out_sq  = out + ND;                   // softmax over tokens [N, M]
    float* out_sm  = out + 2 * ND;               // softmax over slots  [N, M]

    k_norm<<<Ntok / 256, 256>>>(x);
    k_qt<<<dim3(HWc / 32, Dd / 32, Bc), dim3(32, 8)>>>(x);
    k_gemm1<<<Ntok / 32, 256>>>(pmem, out_sq, out_sm);
    k_gemm2<<<Ntok / 32, 256>>>(pmem, out_sm, out_upd);
    k_scale<<<1184, 256>>>(out_sq);
    (void)in_sizes; (void)n_in; (void)out_size;
}

// round 7
// speedup vs baseline: 1.1024x; 1.1024x over previous
#include <cuda_runtime.h>
#include <cuda_bf16.h>
#include <math.h>

typedef unsigned long long u64;

// Problem dims (fixed by the dataset)
#define Bc   8
#define Cc   512
#define Hc   96
#define Wc   144
#define HWc  (Hc * Wc)          // 13824
#define Ntok (Bc * HWc)         // 110592
#define Dd   512
#define Mm   512

#define BK     16
#define BS_LD  516              // padded Bs row stride (floats)
#define AS_LD  66               // padded As2 row stride (floats), 66*4=264 is 8B-aligned

// Packed fp32x2 FMA (Blackwell FFMA2 — only reachable via PTX)
#define FMA_F32X2(d, a, b, c) \
    asm("fma.rn.f32x2 %0, %1, %2, %3;" : "=l"(d) : "l"(a), "l"(b), "l"(c))
#define UNPACK_F32X2(lo, hi, in) \
    asm("mov.b64 {%0, %1}, %2;" : "=r"(lo), "=r"(hi) : "l"(in))

// Scratch (allocation-free rule: __device__ globals)
__device__ float g_q[(size_t)Ntok * Dd];   // normalized q, [N, D] row-major
__device__ float g_inv[Ntok];              // 1/norm per token
__device__ float g_colsum[Mm];             // column softmax denominators

// ---------------------------------------------------------------------------
// K1: per-token inverse L2 norm over channels (coalesced along hw), + zero colsum
// ---------------------------------------------------------------------------
__global__ void k_norm(const float* __restrict__ x) {
    int n = blockIdx.x * 256 + threadIdx.x;
    if (blockIdx.x == 0) {                 // zero ALL 512 entries (idempotent state)
        g_colsum[threadIdx.x]       = 0.0f;
        g_colsum[threadIdx.x + 256] = 0.0f;
    }
    if (n >= Ntok) return;
    int b = n / HWc, hw = n % HWc;
    const float* p = x + (size_t)b * Cc * HWc + hw;
    float s = 0.0f;
#pragma unroll 8
    for (int c = 0; c < Cc; c++) {
        float v = p[(size_t)c * HWc];
        s += v * v;
    }
    g_inv[n] = 1.0f / fmaxf(sqrtf(s), 1e-12f);
}

// ---------------------------------------------------------------------------
// K2: transpose [B,C,HW] -> g_q [N,D] with normalization, 32x32 smem tiles
// ---------------------------------------------------------------------------
__global__ void k_qt(const float* __restrict__ x) {
    __shared__ float tile[32][33];
    int b   = blockIdx.z;
    int hw0 = blockIdx.x * 32;
    int d0  = blockIdx.y * 32;
    for (int r = threadIdx.y; r < 32; r += 8)
        tile[r][threadIdx.x] =
            x[((size_t)(b * Cc + d0 + r)) * HWc + hw0 + threadIdx.x];
    __syncthreads();
    for (int r = threadIdx.y; r < 32; r += 8) {
        int n = b * HWc + hw0 + r;
        g_q[(size_t)n * Dd + d0 + threadIdx.x] = tile[threadIdx.x][r] * g_inv[n];
    }
}

// ---------------------------------------------------------------------------
// Shared FFMA2 mainloop body (A duplicated in smem, B packed from float4).
// acc2[i][jp] = f32x2 pair over slots (2*jp, 2*jp+1) of shelf; i = token micro.
// ---------------------------------------------------------------------------
#define MAINLOOP_KSTEP(As2, Bs, acc2, tg, sg)                                  \
    _Pragma("unroll")                                                          \
    for (int kk = 0; kk < BK; kk++) {                                          \
        double2 bq0 = *(const double2*)&Bs[kk][sg * 4];                        \
        double2 bq1 = *(const double2*)&Bs[kk][256 + sg * 4];                  \
        u64 bb[4];                                                             \
        bb[0] = __double_as_longlong(bq0.x);                                   \
        bb[1] = __double_as_longlong(bq0.y);                                   \
        bb[2] = __double_as_longlong(bq1.x);                                   \
        bb[3] = __double_as_longlong(bq1.y);                                   \
        _Pragma("unroll")                                                      \
        for (int i = 0; i < 8; i++) {                                          \
            int t2 = ((i >> 2) * 16 + tg * 4 + (i & 3)) * 2;                   \
            u64 aa = *(const u64*)&As2[kk][t2];                                \
            _Pragma("unroll")                                                  \
            for (int jp = 0; jp < 4; jp++)                                     \
                FMA_F32X2(acc2[i][jp], aa, bb[jp], acc2[i][jp]);               \
        }                                                                      \
    }

// ---------------------------------------------------------------------------
// K3: GEMM1 (score = q . mem^T) fused with exp, row softmax, colsum reduction,
//     and both score outputs. CTA tile: 32 tokens x 512 slots, 256 threads.
// ---------------------------------------------------------------------------
__global__ void __launch_bounds__(256, 2)
k_gemm1(const float* __restrict__ pmem,
        float* __restrict__ out_sq,
        float* __restrict__ out_sm) {
    __shared__ float As2[BK][AS_LD];
    __shared__ float Bs[BK][BS_LD];
    __shared__ float rs[32];
    __shared__ float cs[Mm];

    int tid = threadIdx.x;
    int sg = tid & 63;          // slot group 0..63
    int tg = tid >> 6;          // token group 0..3
    int n0 = blockIdx.x * 32;

    u64 acc2[8][4];
#pragma unroll
    for (int i = 0; i < 8; i++)
#pragma unroll
        for (int jp = 0; jp < 4; jp++) acc2[i][jp] = 0ull;

    for (int k0 = 0; k0 < Dd; k0 += BK) {
        // A tile, duplicated: As2[kk][2t] = As2[kk][2t+1] = g_q[(n0+t)*D+k0+kk]
        {
            int t  = tid >> 3;
            int kk = (tid & 7) * 2;
            const float* src = &g_q[(size_t)(n0 + t) * Dd + k0 + kk];
            float v0 = src[0], v1 = src[1];
            *(float2*)&As2[kk][2 * t]     = make_float2(v0, v0);
            *(float2*)&As2[kk + 1][2 * t] = make_float2(v1, v1);
        }
        // B tile (transposed): Bs[kk][m] = mem[m*D + k0+kk]
        {
            int q = tid & 3;
            int mb = tid >> 2;
#pragma unroll
            for (int rr = 0; rr < 8; rr++) {
                int m = mb + rr * 64;
                float4 v = *(const float4*)&pmem[(size_t)m * Dd + k0 + q * 4];
                Bs[q * 4 + 0][m] = v.x;
                Bs[q * 4 + 1][m] = v.y;
                Bs[q * 4 + 2][m] = v.z;
                Bs[q * 4 + 3][m] = v.w;
            }
        }
        __syncthreads();
        MAINLOOP_KSTEP(As2, Bs, acc2, tg, sg)
        __syncthreads();
    }

    // ---- epilogue: unpack, exp, row/col reductions, stores ----
    float acc[8][8];
#pragma unroll
    for (int i = 0; i < 8; i++)
#pragma unroll
        for (int jp = 0; jp < 4; jp++) {
            unsigned lo, hi;
            UNPACK_F32X2(lo, hi, acc2[i][jp]);
            acc[i][2 * jp]     = __expf(__uint_as_float(lo));  // |score|<=1: no max-sub
            acc[i][2 * jp + 1] = __expf(__uint_as_float(hi));
        }

    if (tid < 32) rs[tid] = 0.0f;
    cs[tid]       = 0.0f;
    cs[tid + 256] = 0.0f;
    __syncthreads();

#pragma unroll
    for (int i = 0; i < 8; i++) {
        float p = 0.0f;
#pragma unroll
        for (int j = 0; j < 8; j++) p += acc[i][j];
        int t = (i >> 2) * 16 + tg * 4 + (i & 3);
        atomicAdd(&rs[t], p);
    }
#pragma unroll
    for (int j = 0; j < 8; j++) {
        float p = 0.0f;
#pragma unroll
        for (int i = 0; i < 8; i++) p += acc[i][j];
        int m = (j >> 2) * 256 + sg * 4 + (j & 3);
        atomicAdd(&cs[m], p);
    }
    __syncthreads();

    atomicAdd(&g_colsum[tid],       cs[tid]);
    atomicAdd(&g_colsum[tid + 256], cs[tid + 256]);

#pragma unroll
    for (int i = 0; i < 8; i++) {
        int t = (i >> 2) * 16 + tg * 4 + (i & 3);
        size_t n = (size_t)(n0 + t);
        float rinv = 1.0f / rs[t];
#pragma unroll
        for (int sh = 0; sh < 2; sh++) {
            int m = sh * 256 + sg * 4;
            float4 e = make_float4(acc[i][sh * 4 + 0], acc[i][sh * 4 + 1],
                                   acc[i][sh * 4 + 2], acc[i][sh * 4 + 3]);
            *(float4*)&out_sq[n * Mm + m] = e;   // unnormalized exp; scaled in K5
            float4 pv = make_float4(e.x * rinv, e.y * rinv, e.z * rinv, e.w * rinv);
            *(float4*)&out_sm[n * Mm + m] = pv;  // row softmax (final)
        }
    }
}

// ---------------------------------------------------------------------------
// K4: GEMM2 (upd = P . mem), same FFMA2 skeleton; B tile is a straight copy.
//     Output written in [B, D, H, W] layout via chunked smem transpose.
// ---------------------------------------------------------------------------
__global__ void __launch_bounds__(256, 2)
k_gemm2(const float* __restrict__ pmem,
        const float* __restrict__ Pmat,
        float* __restrict__ out_upd) {
    __shared__ float As2[BK][AS_LD];
    __shared__ float Bs[BK][BS_LD];
    __shared__ float sT[32][33];

    int tid = threadIdx.x;
    int sg = tid & 63;
    int tg = tid >> 6;
    int n0 = blockIdx.x * 32;

    u64 acc2[8][4];
#pragma unroll
    for (int i = 0; i < 8; i++)
#pragma unroll
        for (int jp = 0; jp < 4; jp++) acc2[i][jp] = 0ull;

    for (int k0 = 0; k0 < Mm; k0 += BK) {
        {
            int t  = tid >> 3;
            int kk = (tid & 7) * 2;
            const float* src = &Pmat[(size_t)(n0 + t) * Mm + k0 + kk];
            float v0 = src[0], v1 = src[1];
            *(float2*)&As2[kk][2 * t]     = make_float2(v0, v0);
            *(float2*)&As2[kk + 1][2 * t] = make_float2(v1, v1);
        }
        // Bs[kk][d] = mem[(k0+kk)*D + d]  (straight float4 copy)
        {
            int kk = tid >> 7;          // 0..1
            int d4 = (tid & 127) * 4;   // 0..508
#pragma unroll
            for (int rr = 0; rr < 8; rr++) {
                int k = kk + rr * 2;
                float4 v = *(const float4*)&pmem[(size_t)(k0 + k) * Dd + d4];
                *(float4*)&Bs[k][d4] = v;
            }
        }
        __syncthreads();
        MAINLOOP_KSTEP(As2, Bs, acc2, tg, sg)
        __syncthreads();
    }

    float acc[8][8];
#pragma unroll
    for (int i = 0; i < 8; i++)
#pragma unroll
        for (int jp = 0; jp < 4; jp++) {
            unsigned lo, hi;
            UNPACK_F32X2(lo, hi, acc2[i][jp]);
            acc[i][2 * jp]     = __uint_as_float(lo);
            acc[i][2 * jp + 1] = __uint_as_float(hi);
        }

    // Output transpose: upd[(b*D + d)*HW + hw], coalesced via 32-d chunks.
    int b   = n0 / HWc;
    int hw0 = n0 % HWc;
    for (int c = 0; c < 16; c++) {
        int sh   = c >> 3;
        int sglo = (c & 7) * 8;
        if (sg >= sglo && sg < sglo + 8) {
#pragma unroll
            for (int i = 0; i < 8; i++) {
                int t = (i >> 2) * 16 + tg * 4 + (i & 3);
#pragma unroll
                for (int j = 0; j < 4; j++) {
                    int dl = (sg - sglo) * 4 + j;
                    sT[dl][t] = acc[i][sh * 4 + j];
                }
            }
        }
        __syncthreads();
        {
            int t = tid & 31;
#pragma unroll
            for (int r = 0; r < 4; r++) {
                int dl = (tid >> 5) + r * 8;
                int d  = c * 32 + dl;
                out_upd[((size_t)(b * Dd + d)) * HWc + hw0 + t] = sT[dl][t];
            }
        }
        __syncthreads();
    }
}

// ---------------------------------------------------------------------------
// K5: scale unnormalized exp by 1/colsum (column softmax finalization)
// ---------------------------------------------------------------------------
__global__ void k_scale(float* __restrict__ out_sq) {
    __shared__ float cinv[Mm];
    int tid = threadIdx.x;
    cinv[tid]       = 1.0f / g_colsum[tid];
    cinv[tid + 256] = 1.0f / g_colsum[tid + 256];
    __syncthreads();
    size_t total4 = (size_t)Ntok * Mm / 4;
    for (size_t i = (size_t)blockIdx.x * 256 + tid; i < total4;
         i += (size_t)gridDim.x * 256) {
        float4 v = ((float4*)out_sq)[i];
        int m = (int)((i * 4) & (Mm - 1));
        v.x *= cinv[m];
        v.y *= cinv[m + 1];
        v.z *= cinv[m + 2];
        v.w *= cinv[m + 3];
        ((float4*)out_sq)[i] = v;
    }
}

// ---------------------------------------------------------------------------
extern "C" void kernel_launch(void* const* d_in, const int* in_sizes, int n_in,
                              void* d_out, int out_size) {
    const float* x    = (const float*)d_in[0];   // query_source [8,512,96,144]
    const float* pmem = (const float*)d_in[1];   // memory [512,512]
    float* out = (float*)d_out;

    const size_t ND = (size_t)Ntok * Dd;         // 56,623,104
    float* out_upd = out;                        // [B, D, H, W]
    float* out_sq  = out + ND;                   // softmax over tokens [N, M]
    float* out_sm  = out + 2 * ND;               // softmax over slots  [N, M]

    k_norm<<<Ntok / 256, 256>>>(x);
    k_qt<<<dim3(HWc / 32, Dd / 32, Bc), dim3(32, 8)>>>(x);
    k_gemm1<<<Ntok / 32, 256>>>(pmem, out_sq, out_sm);
    k_gemm2<<<Ntok / 32, 256>>>(pmem, out_sm, out_upd);
    k_scale<<<1184, 256>>>(out_sq);
    (void)in_sizes; (void)n_in; (void)out_size;
}

// round 9
// speedup vs baseline: 1.2885x; 1.1688x over previous
#include <cuda_runtime.h>
#include <cuda_bf16.h>
#include <math.h>
#include <cstdint>

typedef unsigned long long u64;

// Problem dims (fixed by the dataset)
#define Bc   8
#define Cc   512
#define Hc   96
#define Wc   144
#define HWc  (Hc * Wc)          // 13824
#define Ntok (Bc * HWc)         // 110592
#define Dd   512
#define Mm   512

#define BK     16
#define AS_LD  66               // padded duplicated-A row stride (floats)
#define BS_LD  516              // padded B row stride (floats); 2064B, 16B-aligned
#define A_BUF  (BK * AS_LD)     // 1056 floats per A buffer
#define B_BUF  (BK * BS_LD)     // 8256 floats per B buffer
#define EXTRA_OFF (2 * A_BUF + 2 * B_BUF)   // 18624 floats
#define SMEM_DYN  ((EXTRA_OFF + 1088) * 4)  // 78848 B (extra: cs/rs or sT)

// Packed fp32x2 FMA (Blackwell FFMA2 — only reachable via PTX)
#define FMA_F32X2(d, a, b, c) \
    asm("fma.rn.f32x2 %0, %1, %2, %3;" : "=l"(d) : "l"(a), "l"(b), "l"(c))
#define UNPACK_F32X2(lo, hi, in) \
    asm("mov.b64 {%0, %1}, %2;" : "=r"(lo), "=r"(hi) : "l"(in))

#define CP_ASYNC16(dst, src) \
    asm volatile("cp.async.ca.shared.global [%0], [%1], 16;" :: "r"(dst), "l"(src))
#define CP_COMMIT()  asm volatile("cp.async.commit_group;" ::: "memory")
#define CP_WAIT0()   asm volatile("cp.async.wait_group 0;" ::: "memory")

__device__ __forceinline__ uint32_t smem_u32(const void* p) {
    uint32_t a;
    asm("{ .reg .u64 t; cvta.to.shared.u64 t, %1; cvt.u32.u64 %0, t; }"
        : "=r"(a) : "l"(p));
    return a;
}

// Scratch (allocation-free rule: __device__ globals)
__device__ float g_q[(size_t)Ntok * Dd];   // normalized q, [N, D] row-major
__device__ float g_memT[Dd * Mm];          // memory transposed: [d][m]
__device__ float g_inv[Ntok];              // 1/norm per token
__device__ float g_colsum[Mm];             // column softmax denominators

// ---------------------------------------------------------------------------
// K1: per-token inverse L2 norm over channels (coalesced along hw), + zero colsum
// ---------------------------------------------------------------------------
__global__ void k_norm(const float* __restrict__ x) {
    int n = blockIdx.x * 256 + threadIdx.x;
    if (blockIdx.x == 0) {                 // zero ALL 512 entries (idempotent state)
        g_colsum[threadIdx.x]       = 0.0f;
        g_colsum[threadIdx.x + 256] = 0.0f;
    }
    if (n >= Ntok) return;
    int b = n / HWc, hw = n % HWc;
    const float* p = x + (size_t)b * Cc * HWc + hw;
    float s = 0.0f;
#pragma unroll 8
    for (int c = 0; c < Cc; c++) {
        float v = p[(size_t)c * HWc];
        s += v * v;
    }
    g_inv[n] = 1.0f / fmaxf(sqrtf(s), 1e-12f);
}

// ---------------------------------------------------------------------------
// K2: transpose mem [m][d] -> g_memT [d][m] (one-time, 1MB)
// ---------------------------------------------------------------------------
__global__ void k_prepT(const float* __restrict__ pmem) {
    __shared__ float t[32][33];
    int d0 = blockIdx.x * 32;
    int m0 = blockIdx.y * 32;
    for (int r = threadIdx.y; r < 32; r += 8)
        t[r][threadIdx.x] = pmem[(size_t)(m0 + r) * Dd + d0 + threadIdx.x];
    __syncthreads();
    for (int r = threadIdx.y; r < 32; r += 8)
        g_memT[(size_t)(d0 + r) * Mm + m0 + threadIdx.x] = t[threadIdx.x][r];
}

// ---------------------------------------------------------------------------
// K3: transpose [B,C,HW] -> g_q [N,D] with normalization, 32x32 smem tiles
// ---------------------------------------------------------------------------
__global__ void k_qt(const float* __restrict__ x) {
    __shared__ float tile[32][33];
    int b   = blockIdx.z;
    int hw0 = blockIdx.x * 32;
    int d0  = blockIdx.y * 32;
    for (int r = threadIdx.y; r < 32; r += 8)
        tile[r][threadIdx.x] =
            x[((size_t)(b * Cc + d0 + r)) * HWc + hw0 + threadIdx.x];
    __syncthreads();
    for (int r = threadIdx.y; r < 32; r += 8) {
        int n = b * HWc + hw0 + r;
        g_q[(size_t)n * Dd + d0 + threadIdx.x] = tile[threadIdx.x][r] * g_inv[n];
    }
}

// ---------------------------------------------------------------------------
// FFMA2 compute for one BK=16 k-step (A duplicated pairs, B packed from smem)
// ---------------------------------------------------------------------------
#define COMPUTE_KSTEP(As2, Bs, acc2, tg, sg)                                   \
    _Pragma("unroll")                                                          \
    for (int kk = 0; kk < BK; kk++) {                                          \
        double2 bq0 = *(const double2*)&(Bs)[kk][(sg) * 4];                    \
        double2 bq1 = *(const double2*)&(Bs)[kk][256 + (sg) * 4];              \
        u64 bb[4];                                                             \
        bb[0] = __double_as_longlong(bq0.x);                                   \
        bb[1] = __double_as_longlong(bq0.y);                                   \
        bb[2] = __double_as_longlong(bq1.x);                                   \
        bb[3] = __double_as_longlong(bq1.y);                                   \
        _Pragma("unroll")                                                      \
        for (int i = 0; i < 8; i++) {                                          \
            int t2 = ((i >> 2) * 16 + (tg) * 4 + (i & 3)) * 2;                 \
            u64 aa = *(const u64*)&(As2)[kk][t2];                              \
            _Pragma("unroll")                                                  \
            for (int jp = 0; jp < 4; jp++)                                     \
                FMA_F32X2(acc2[i][jp], aa, bb[jp], acc2[i][jp]);               \
        }                                                                      \
    }

// ---------------------------------------------------------------------------
// Pipelined mainloop (2-stage cp.async double buffer, 1 barrier per k-step).
// A: [N,512] row-major (32 rows used), Bsrc: rows k of a [512,512] matrix.
// ---------------------------------------------------------------------------
__device__ __forceinline__ void run_mainloop(
    const float* __restrict__ A, const float* __restrict__ Bsrc,
    float* dynsm, uint32_t sb, int n0, int tid, int tg, int sg,
    u64 acc2[8][4]) {

    const int t   = tid >> 3;
    const int kkA = (tid & 7) * 2;
    const size_t arow = (size_t)(n0 + t) * 512 + kkA;

    // ---- prologue: stage k0=0 into buffer 0 ----
    {
#pragma unroll
        for (int i = 0; i < 8; i++) {
            int chunk = tid + i * 256;
            int r = chunk >> 7, c = (chunk & 127) * 4;
            uint32_t dst = sb + (uint32_t)(2 * A_BUF + r * BS_LD + c) * 4;
            CP_ASYNC16(dst, Bsrc + (size_t)r * 512 + c);
        }
        CP_COMMIT();
        float2 av = *(const float2*)&A[arow];
        float* As0 = dynsm;
        *(float2*)&As0[kkA * AS_LD + 2 * t]       = make_float2(av.x, av.x);
        *(float2*)&As0[(kkA + 1) * AS_LD + 2 * t] = make_float2(av.y, av.y);
        CP_WAIT0();
        __syncthreads();
    }

    int buf = 0;
    for (int k0 = 0; k0 < 512; k0 += BK) {
        float2 av;
        if (k0 < 512 - BK) {
            int nb = buf ^ 1;
#pragma unroll
            for (int i = 0; i < 8; i++) {
                int chunk = tid + i * 256;
                int r = chunk >> 7, c = (chunk & 127) * 4;
                uint32_t dst = sb + (uint32_t)(2 * A_BUF + nb * B_BUF + r * BS_LD + c) * 4;
                CP_ASYNC16(dst, Bsrc + (size_t)(k0 + BK + r) * 512 + c);
            }
            CP_COMMIT();
            av = *(const float2*)&A[arow + k0 + BK];
        }
        {
            const float (*As2)[AS_LD] = (const float(*)[AS_LD])(dynsm + buf * A_BUF);
            const float (*Bs)[BS_LD]  = (const float(*)[BS_LD])(dynsm + 2 * A_BUF + buf * B_BUF);
            COMPUTE_KSTEP(As2, Bs, acc2, tg, sg)
        }
        if (k0 < 512 - BK) {
            float* Asn = dynsm + (buf ^ 1) * A_BUF;
            Asn[kkA * AS_LD + 2 * t]           = av.x;
            Asn[kkA * AS_LD + 2 * t + 1]       = av.x;
            Asn[(kkA + 1) * AS_LD + 2 * t]     = av.y;
            Asn[(kkA + 1) * AS_LD + 2 * t + 1] = av.y;
            CP_WAIT0();
        }
        __syncthreads();
        buf ^= 1;
    }
}

// ---------------------------------------------------------------------------
// K4: GEMM1 (score = q . mem^T) fused with exp, row softmax, colsum reduction,
//     and both score outputs. CTA tile: 32 tokens x 512 slots, 256 threads.
// ---------------------------------------------------------------------------
__global__ void __launch_bounds__(256, 2)
k_gemm1(float* __restrict__ out_sq, float* __restrict__ out_sm) {
    extern __shared__ float dynsm[];
    uint32_t sb = smem_u32(dynsm);
    float* rs = dynsm + EXTRA_OFF;        // 32 floats
    float* cs = dynsm + EXTRA_OFF + 32;   // 512 floats

    int tid = threadIdx.x;
    int sg = tid & 63;
    int tg = tid >> 6;
    int n0 = blockIdx.x * 32;

    u64 acc2[8][4];
#pragma unroll
    for (int i = 0; i < 8; i++)
#pragma unroll
        for (int jp = 0; jp < 4; jp++) acc2[i][jp] = 0ull;

    run_mainloop(g_q, g_memT, dynsm, sb, n0, tid, tg, sg, acc2);

    // ---- epilogue: unpack, exp, row/col reductions, stores ----
    float acc[8][8];
#pragma unroll
    for (int i = 0; i < 8; i++)
#pragma unroll
        for (int jp = 0; jp < 4; jp++) {
            unsigned lo, hi;
            UNPACK_F32X2(lo, hi, acc2[i][jp]);
            acc[i][2 * jp]     = __expf(__uint_as_float(lo));  // |score|<=1: no max-sub
            acc[i][2 * jp + 1] = __expf(__uint_as_float(hi));
        }

    if (tid < 32) rs[tid] = 0.0f;
    cs[tid]       = 0.0f;
    cs[tid + 256] = 0.0f;
    __syncthreads();

#pragma unroll
    for (int i = 0; i < 8; i++) {
        float p = 0.0f;
#pragma unroll
        for (int j = 0; j < 8; j++) p += acc[i][j];
        int t = (i >> 2) * 16 + tg * 4 + (i & 3);
        atomicAdd(&rs[t], p);
    }
#pragma unroll
    for (int j = 0; j < 8; j++) {
        float p = 0.0f;
#pragma unroll
        for (int i = 0; i < 8; i++) p += acc[i][j];
        int m = (j >> 2) * 256 + sg * 4 + (j & 3);
        atomicAdd(&cs[m], p);
    }
    __syncthreads();

    atomicAdd(&g_colsum[tid],       cs[tid]);
    atomicAdd(&g_colsum[tid + 256], cs[tid + 256]);

#pragma unroll
    for (int i = 0; i < 8; i++) {
        int t = (i >> 2) * 16 + tg * 4 + (i & 3);
        size_t n = (size_t)(n0 + t);
        float rinv = 1.0f / rs[t];
#pragma unroll
        for (int sh = 0; sh < 2; sh++) {
            int m = sh * 256 + sg * 4;
            float4 e = make_float4(acc[i][sh * 4 + 0], acc[i][sh * 4 + 1],
                                   acc[i][sh * 4 + 2], acc[i][sh * 4 + 3]);
            *(float4*)&out_sq[n * Mm + m] = e;   // unnormalized exp; scaled in K6
            float4 pv = make_float4(e.x * rinv, e.y * rinv, e.z * rinv, e.w * rinv);
            *(float4*)&out_sm[n * Mm + m] = pv;  // row softmax (final)
        }
    }
}

// ---------------------------------------------------------------------------
// K5: GEMM2 (upd = P . mem), same pipelined skeleton; B = mem rows (straight).
//     Output written in [B, D, H, W] layout via chunked smem transpose.
// ---------------------------------------------------------------------------
__global__ void __launch_bounds__(256, 2)
k_gemm2(const float* __restrict__ pmem,
        const float* __restrict__ Pmat,
        float* __restrict__ out_upd) {
    extern __shared__ float dynsm[];
    uint32_t sb = smem_u32(dynsm);
    float* sT = dynsm + EXTRA_OFF;        // [32][33]

    int tid = threadIdx.x;
    int sg = tid & 63;
    int tg = tid >> 6;
    int n0 = blockIdx.x * 32;

    u64 acc2[8][4];
#pragma unroll
    for (int i = 0; i < 8; i++)
#pragma unroll
        for (int jp = 0; jp < 4; jp++) acc2[i][jp] = 0ull;

    run_mainloop(Pmat, pmem, dynsm, sb, n0, tid, tg, sg, acc2);

    float acc[8][8];
#pragma unroll
    for (int i = 0; i < 8; i++)
#pragma unroll
        for (int jp = 0; jp < 4; jp++) {
            unsigned lo, hi;
            UNPACK_F32X2(lo, hi, acc2[i][jp]);
            acc[i][2 * jp]     = __uint_as_float(lo);
            acc[i][2 * jp + 1] = __uint_as_float(hi);
        }

    // Output transpose: upd[(b*D + d)*HW + hw], coalesced via 32-d chunks.
    int b   = n0 / HWc;
    int hw0 = n0 % HWc;
    for (int c = 0; c < 16; c++) {
        int sh   = c >> 3;
        int sglo = (c & 7) * 8;
        if (sg >= sglo && sg < sglo + 8) {
#pragma unroll
            for (int i = 0; i < 8; i++) {
                int t = (i >> 2) * 16 + tg * 4 + (i & 3);
#pragma unroll
                for (int j = 0; j < 4; j++) {
                    int dl = (sg - sglo) * 4 + j;
                    sT[dl * 33 + t] = acc[i][sh * 4 + j];
                }
            }
        }
        __syncthreads();
        {
            int t = tid & 31;
#pragma unroll
            for (int r = 0; r < 4; r++) {
                int dl = (tid >> 5) + r * 8;
                int d  = c * 32 + dl;
                out_upd[((size_t)(b * Dd + d)) * HWc + hw0 + t] = sT[dl * 33 + t];
            }
        }
        __syncthreads();
    }
}

// ---------------------------------------------------------------------------
// K6: scale unnormalized exp by 1/colsum (column softmax finalization)
// ---------------------------------------------------------------------------
__global__ void k_scale(float* __restrict__ out_sq) {
    __shared__ float cinv[Mm];
    int tid = threadIdx.x;
    cinv[tid]       = 1.0f / g_colsum[tid];
    cinv[tid + 256] = 1.0f / g_colsum[tid + 256];
    __syncthreads();
    size_t total4 = (size_t)Ntok * Mm / 4;
    for (size_t i = (size_t)blockIdx.x * 256 + tid; i < total4;
         i += (size_t)gridDim.x * 256) {
        float4 v = ((float4*)out_sq)[i];
        int m = (int)((i * 4) & (Mm - 1));
        v.x *= cinv[m];
        v.y *= cinv[m + 1];
        v.z *= cinv[m + 2];
        v.w *= cinv[m + 3];
        ((float4*)out_sq)[i] = v;
    }
}

// ---------------------------------------------------------------------------
extern "C" void kernel_launch(void* const* d_in, const int* in_sizes, int n_in,
                              void* d_out, int out_size) {
    const float* x    = (const float*)d_in[0];   // query_source [8,512,96,144]
    const float* pmem = (const float*)d_in[1];   // memory [512,512]
    float* out = (float*)d_out;

    const size_t ND = (size_t)Ntok * Dd;         // 56,623,104
    float* out_upd = out;                        // [B, D, H, W]
    float* out_sq  = out + ND;                   // softmax over tokens [N, M]
    float* out_sm  = out + 2 * ND;               // softmax over slots  [N, M]

    // Idempotent, capture-safe (not a stream op); needed for >48KB dynamic smem
    cudaFuncSetAttribute(k_gemm1, cudaFuncAttributeMaxDynamicSharedMemorySize, SMEM_DYN);
    cudaFuncSetAttribute(k_gemm2, cudaFuncAttributeMaxDynamicSharedMemorySize, SMEM_DYN);

    k_norm<<<Ntok / 256, 256>>>(x);
    k_prepT<<<dim3(16, 16), dim3(32, 8)>>>(pmem);
    k_qt<<<dim3(HWc / 32, Dd / 32, Bc), dim3(32, 8)>>>(x);
    k_gemm1<<<Ntok / 32, 256, SMEM_DYN>>>(out_sq, out_sm);
    k_gemm2<<<Ntok / 32, 256, SMEM_DYN>>>(pmem, out_sm, out_upd);
    k_scale<<<1184, 256>>>(out_sq);
    (void)in_sizes; (void)n_in; (void)out_size;
}